// round 8
// baseline (speedup 1.0000x reference)
#include <cuda_runtime.h>
#include <math.h>
#include <stdint.h>

#define DM   1024
#define SEQ  1024
#define BB   8
#define NH   16
#define HD   64
#define TKN  (BB*SEQ)      /* 8192 tokens */
#define MH   2048
#define NE   4

/* ------------------------------ scratch ------------------------------ */
__device__ float g_Tr[BB*SEQ*DM];
__device__ float g_S [BB*SEQ*DM];
__device__ float g_Sn[BB*SEQ*DM];
__device__ float g_q [BB*NH*SEQ*HD];
__device__ float g_k [BB*NH*SEQ*HD];
__device__ float g_v [BB*NH*SEQ*HD];
__device__ float g_att[(long long)BB*NH*SEQ*SEQ];   /* 512 MB */
__device__ float g_y [BB*NH*SEQ*HD];
__device__ float g_yt[TKN*DM];
__device__ float g_xs[TKN*DM];
__device__ float g_xf[TKN*DM];
__device__ float g_gates[TKN*NE];
__device__ float g_hbuf[TKN*MH];         /* 64 MB */
__device__ float g_aux[8];
__device__ int   g_cnt[NE];
__device__ int   g_list[NE*TKN];
__device__ float g_wl[NE*TKN];

/* --------------------------- reductions ------------------------------ */
__device__ __forceinline__ float blockSum(float v, float* sh) {
    #pragma unroll
    for (int o = 16; o > 0; o >>= 1) v += __shfl_xor_sync(0xffffffffu, v, o);
    int w = threadIdx.x >> 5, l = threadIdx.x & 31;
    __syncthreads();
    if (l == 0) sh[w] = v;
    __syncthreads();
    int nw = blockDim.x >> 5;
    if (w == 0) {
        float x = (l < nw) ? sh[l] : 0.f;
        #pragma unroll
        for (int o = 4; o > 0; o >>= 1) x += __shfl_xor_sync(0xffffffffu, x, o);
        if (l == 0) sh[0] = x;
    }
    __syncthreads();
    return sh[0];
}

__device__ __forceinline__ float blockMax(float v, float* sh) {
    #pragma unroll
    for (int o = 16; o > 0; o >>= 1) v = fmaxf(v, __shfl_xor_sync(0xffffffffu, v, o));
    int w = threadIdx.x >> 5, l = threadIdx.x & 31;
    __syncthreads();
    if (l == 0) sh[w] = v;
    __syncthreads();
    int nw = blockDim.x >> 5;
    if (w == 0) {
        float x = (l < nw) ? sh[l] : -1e30f;
        #pragma unroll
        for (int o = 4; o > 0; o >>= 1) x = fmaxf(x, __shfl_xor_sync(0xffffffffu, x, o));
        if (l == 0) sh[0] = x;
    }
    __syncthreads();
    return sh[0];
}

/* ------------------------- trend decomposition ----------------------- */
__global__ void trend_kernel(const float* __restrict__ x,
                             const float* __restrict__ dw7,
                             const float* __restrict__ dw25,
                             const float* __restrict__ dw49,
                             const float* __restrict__ alpha,
                             float* __restrict__ Tr, float* __restrict__ S) {
    int d = blockIdx.x * 256 + threadIdx.x;
    int n = blockIdx.y, b = blockIdx.z;
    float a0 = alpha[0], a1 = alpha[1], a2 = alpha[2];
    float mx = fmaxf(a0, fmaxf(a1, a2));
    float e0 = expf(a0 - mx), e1 = expf(a1 - mx), e2 = expf(a2 - mx);
    float inv = 1.f / (e0 + e1 + e2);
    float w0 = e0 * inv, w1 = e1 * inv, w2 = e2 * inv;

    const float* xc = x + ((long long)b * SEQ) * DM + d;
    float t7 = 0.f, t25 = 0.f, t49 = 0.f, center = 0.f;
    #pragma unroll
    for (int o = -24; o <= 24; o++) {
        int src = n + o;
        if (src < 0) src = -src;
        else if (src >= SEQ) src = 2 * SEQ - 2 - src;
        float v = xc[(long long)src * DM];
        if (o == 0) center = v;
        t49 += v * dw49[d * 49 + (o + 24)];
        if (o >= -12 && o <= 12) t25 += v * dw25[d * 25 + (o + 12)];
        if (o >= -3  && o <= 3 ) t7  += v * dw7 [d * 7  + (o + 3)];
    }
    float tr = w0 * t7 + w1 * t25 + w2 * t49;
    long long idx = ((long long)b * SEQ + n) * DM + d;
    Tr[idx] = tr;
    S[idx]  = center - tr;
}

/* ------------------------------ LayerNorm ---------------------------- */
__global__ void ln_kernel(const float* __restrict__ in, float* __restrict__ out,
                          const float* __restrict__ g, const float* __restrict__ b) {
    __shared__ float sh[32];
    long long row = blockIdx.x;
    const float* xr = in + row * DM;
    float* orow = out + row * DM;
    int t = threadIdx.x;
    float v[4]; float s = 0.f, sq = 0.f;
    #pragma unroll
    for (int a = 0; a < 4; a++) {
        int j = t + a * 256;
        v[a] = xr[j]; s += v[a]; sq += v[a] * v[a];
    }
    s  = blockSum(s,  sh);
    sq = blockSum(sq, sh);
    float mean = s * (1.f / DM);
    float var  = sq * (1.f / DM) - mean * mean;
    float rstd = rsqrtf(var + 1e-5f);
    #pragma unroll
    for (int a = 0; a < 4; a++) {
        int j = t + a * 256;
        orow[j] = (v[a] - mean) * rstd * g[j] + b[j];
    }
}

/* --------------------------- TF32 tensor GEMM ------------------------- */
/* C[M,N] = A[M,K] @ (BT ? B[N,K]^T : B[K,N]) with fused epilogue.
 * 128x128x32 CTA tile, 256 threads = 8 warps, warp tile 64x32,
 * mma.sync.m16n8k8.tf32, cp.async 2-stage, in-smem RNA tf32 convert pass.
 * Optional token gather (A rows) / scatter (C rows) for sparse MoE. */
enum { FLAG_GELU = 1, FLAG_ACCUM = 2, FLAG_PERM = 4, FLAG_GATHER = 8, FLAG_SCATTER = 16 };

#define AST 36     /* padded stride of A / BT-B smem rows (floats) */
#define BNN 132    /* padded stride of NN-B smem rows (floats) */
#define ABUF 4608  /* 128*36 floats, >= 32*132 = 4224 too */
#define GEMM_SMEM (4 * ABUF * 4 + 512)

__device__ __forceinline__ uint32_t f2tf(float f) {
    uint32_t u;
    asm("cvt.rna.tf32.f32 %0, %1;" : "=r"(u) : "f"(f));
    return u;
}

__device__ __forceinline__ void cpa16(float* dst, const float* src, bool pred) {
    uint32_t d = (uint32_t)__cvta_generic_to_shared(dst);
    int sz = pred ? 16 : 0;
    asm volatile("cp.async.cg.shared.global [%0], [%1], 16, %2;"
                 :: "r"(d), "l"(src), "r"(sz));
}

#define MMA8(d, av, bv) \
    asm volatile("mma.sync.aligned.m16n8k8.row.col.f32.tf32.tf32.f32 " \
        "{%0,%1,%2,%3},{%4,%5,%6,%7},{%8,%9},{%0,%1,%2,%3};" \
        : "+f"((d)[0]), "+f"((d)[1]), "+f"((d)[2]), "+f"((d)[3]) \
        : "r"((av)[0]), "r"((av)[1]), "r"((av)[2]), "r"((av)[3]), \
          "r"((bv)[0]), "r"((bv)[1]))

template<bool BT>
__global__ __launch_bounds__(256) void gemm_tc(
    const float* __restrict__ A, const float* __restrict__ Bm,
    const float* __restrict__ bias, const float* __restrict__ resid,
    const float* __restrict__ rowScale, int rsStride,
    const int* __restrict__ rowIdx, const int* __restrict__ cntP,
    float* __restrict__ C, int M, int N, int K,
    long long sA, long long sB, long long sC, int flags) {
    extern __shared__ float sm[];
    float* As = sm;              /* 2 x ABUF */
    float* Bs = sm + 2 * ABUF;   /* 2 x ABUF */
    int*   ridx = (int*)(sm + 4 * ABUF);  /* 128 ints: global A-row per tile row */
    int z = blockIdx.z;
    A  += (long long)z * sA;
    Bm += (long long)z * sB;
    C  += (long long)z * sC;
    int m0 = blockIdx.y * 128, n0 = blockIdx.x * 128;
    int cntV = cntP ? cntP[0] : M;
    if (m0 >= cntV) return;
    int tid = threadIdx.x;
    int lane = tid & 31, warp = tid >> 5;
    int wm = (warp & 1) * 64;
    int wn = (warp >> 1) * 32;
    int g = lane >> 2, qd = lane & 3;

    if (flags & FLAG_GATHER) {
        if (tid < 128) {
            int s = m0 + tid; if (s >= cntV) s = cntV - 1;
            ridx[tid] = rowIdx[s];
        }
    } else {
        if (tid < 128) ridx[tid] = m0 + tid;
    }
    __syncthreads();

    float acc[4][4][4];
    #pragma unroll
    for (int i = 0; i < 4; i++)
        #pragma unroll
        for (int j = 0; j < 4; j++)
            #pragma unroll
            for (int l = 0; l < 4; l++) acc[i][j][l] = 0.f;

    auto prefetch = [&](int kt, int buf) {
        int k0 = kt * 32;
        float* as = As + buf * ABUF;
        float* bs = Bs + buf * ABUF;
        #pragma unroll
        for (int i = 0; i < 4; i++) {
            int c = tid + i * 256;          /* 0..1023 */
            int row = c >> 3, cc = (c & 7) * 4;
            cpa16(&as[row * AST + cc], A + (long long)ridx[row] * K + k0 + cc, true);
        }
        if (BT) {
            #pragma unroll
            for (int i = 0; i < 4; i++) {
                int c = tid + i * 256;
                int row = c >> 3, cc = (c & 7) * 4;
                bool p = (n0 + row) < N;
                const float* src = p ? (Bm + (long long)(n0 + row) * K + k0 + cc) : Bm;
                cpa16(&bs[row * AST + cc], src, p);
            }
        } else {
            #pragma unroll
            for (int i = 0; i < 4; i++) {
                int c = tid + i * 256;
                int row = c >> 5, cc = (c & 31) * 4;
                bool p = (n0 + cc) < N;
                const float* src = p ? (Bm + (long long)(k0 + row) * N + n0 + cc) : Bm;
                cpa16(&bs[row * BNN + cc], src, p);
            }
        }
    };

    const int KT = K / 32;
    prefetch(0, 0);
    asm volatile("cp.async.commit_group;");
    for (int kt = 0; kt < KT; kt++) {
        if (kt + 1 < KT) {
            prefetch(kt + 1, (kt + 1) & 1);
            asm volatile("cp.async.commit_group;");
            asm volatile("cp.async.wait_group 1;");
        } else {
            asm volatile("cp.async.wait_group 0;");
        }
        __syncthreads();
        float* asw = As + (kt & 1) * ABUF;
        float* bsw = Bs + (kt & 1) * ABUF;
        /* ---- in-place RNA fp32->tf32 convert (each element once) ---- */
        #pragma unroll
        for (int i = 0; i < 4; i++) {
            int c = tid + i * 256;                 /* 0..1023 */
            int r = c >> 3, c4 = (c & 7) * 4;
            float4 v = *(float4*)&asw[r * AST + c4];
            uint4 u;
            u.x = f2tf(v.x); u.y = f2tf(v.y); u.z = f2tf(v.z); u.w = f2tf(v.w);
            *(uint4*)&asw[r * AST + c4] = u;
        }
        #pragma unroll
        for (int i = 0; i < 4; i++) {
            int c = tid + i * 256;
            int r, c4, off;
            if (BT) { r = c >> 3; c4 = (c & 7) * 4; off = r * AST + c4; }
            else    { r = c >> 5; c4 = (c & 31) * 4; off = r * BNN + c4; }
            float4 v = *(float4*)&bsw[off];
            uint4 u;
            u.x = f2tf(v.x); u.y = f2tf(v.y); u.z = f2tf(v.z); u.w = f2tf(v.w);
            *(uint4*)&bsw[off] = u;
        }
        __syncthreads();
        const uint32_t* as = (const uint32_t*)asw;
        const uint32_t* bs = (const uint32_t*)bsw;
        #pragma unroll
        for (int ks = 0; ks < 4; ks++) {
            int k8 = ks * 8;
            uint32_t a[4][4], b[4][2];
            #pragma unroll
            for (int mi = 0; mi < 4; mi++) {
                int r = wm + mi * 16 + g;
                a[mi][0] = as[r * AST + k8 + qd];
                a[mi][1] = as[(r + 8) * AST + k8 + qd];
                a[mi][2] = as[r * AST + k8 + qd + 4];
                a[mi][3] = as[(r + 8) * AST + k8 + qd + 4];
            }
            #pragma unroll
            for (int ni = 0; ni < 4; ni++) {
                int cn = wn + ni * 8 + g;
                if (BT) {
                    b[ni][0] = bs[cn * AST + k8 + qd];
                    b[ni][1] = bs[cn * AST + k8 + qd + 4];
                } else {
                    b[ni][0] = bs[(k8 + qd) * BNN + cn];
                    b[ni][1] = bs[(k8 + qd + 4) * BNN + cn];
                }
            }
            #pragma unroll
            for (int mi = 0; mi < 4; mi++)
                #pragma unroll
                for (int ni = 0; ni < 4; ni++)
                    MMA8(acc[mi][ni], a[mi], b[ni]);
        }
        __syncthreads();
    }

    auto epi = [&](int m, int n, float v) {
        if (n >= N) return;
        if ((flags & FLAG_SCATTER) && m >= cntV) return;
        if (bias) v += bias[n];
        if (flags & FLAG_GELU) v = 0.5f * v * (1.f + erff(v * 0.70710678118654752f));
        if (rowScale) v *= rowScale[(long long)m * rsStride];
        int om = (flags & FLAG_SCATTER) ? rowIdx[m] : m;
        if (resid) v += resid[(long long)om * N + n];
        long long idx;
        if (flags & FLAG_PERM) {
            int b_ = om >> 10, ns = om & 1023, h = n >> 6, d = n & 63;
            idx = ((long long)(b_ * NH + h) * SEQ + ns) * HD + d;
        } else {
            idx = (long long)om * N + n;
        }
        if (flags & FLAG_ACCUM) C[idx] += v; else C[idx] = v;
    };

    #pragma unroll
    for (int mi = 0; mi < 4; mi++)
        #pragma unroll
        for (int ni = 0; ni < 4; ni++) {
            int m = m0 + wm + mi * 16 + g;
            int n = n0 + wn + ni * 8 + qd * 2;
            float* c4 = acc[mi][ni];
            epi(m,     n,     c4[0]);
            epi(m,     n + 1, c4[1]);
            epi(m + 8, n,     c4[2]);
            epi(m + 8, n + 1, c4[3]);
        }
}

/* ------------------------- ALiBi softmax ------------------------------ */
__global__ void softmax_alibi_kernel(float* __restrict__ att) {
    __shared__ float sh[32];
    int i = blockIdx.x;
    int bh = blockIdx.y;
    int h = bh & (NH - 1);
    float slope = exp2f(-0.5f * (float)(h + 1));
    float* row = att + ((long long)bh * SEQ + i) * SEQ;
    int t = threadIdx.x;
    float v[4]; float mx = -1e30f;
    #pragma unroll
    for (int a = 0; a < 4; a++) {
        int j = t + a * 256;
        float dist = (j > i) ? (float)(j - i) : 0.f;
        v[a] = row[j] * 0.125f - slope * dist;
        mx = fmaxf(mx, v[a]);
    }
    mx = blockMax(mx, sh);
    float s = 0.f;
    #pragma unroll
    for (int a = 0; a < 4; a++) { v[a] = expf(v[a] - mx); s += v[a]; }
    s = blockSum(s, sh);
    float inv = 1.f / s;
    #pragma unroll
    for (int a = 0; a < 4; a++) row[t + a * 256] = v[a] * inv;
}

/* ---------------- attention output permute [b,h,n,d]->[b,n,D] --------- */
__global__ void permute_y_kernel(const float* __restrict__ y, float* __restrict__ out) {
    long long idx = (long long)blockIdx.x * 256 + threadIdx.x;
    int dfull = (int)(idx & 1023);
    int n = (int)((idx >> 10) & 1023);
    int b = (int)(idx >> 20);
    int h = dfull >> 6, d = dfull & 63;
    out[idx] = y[((long long)(b * NH + h) * SEQ + n) * HD + d];
}

/* ------------------- router top-2, gather lists, aux ------------------ */
__global__ void zero_aux_kernel(float* a, int* c) {
    if (threadIdx.x < 8) a[threadIdx.x] = 0.f;
    if (threadIdx.x < NE) c[threadIdx.x] = 0;
}

__global__ void topk_kernel(const float* __restrict__ gl,
                            int* __restrict__ cnt, int* __restrict__ list,
                            float* __restrict__ wl, float* __restrict__ aux) {
    int t0 = blockIdx.x * blockDim.x + threadIdx.x;
    float g[4];
    #pragma unroll
    for (int e = 0; e < 4; e++) g[e] = gl[t0 * 4 + e];
    float mx = fmaxf(fmaxf(g[0], g[1]), fmaxf(g[2], g[3]));
    float s = 0.f;
    #pragma unroll
    for (int e = 0; e < 4; e++) { g[e] = expf(g[e] - mx); s += g[e]; }
    float inv = 1.f / s;
    #pragma unroll
    for (int e = 0; e < 4; e++) g[e] *= inv;
    int i1 = 0;
    #pragma unroll
    for (int e = 1; e < 4; e++) if (g[e] > g[i1]) i1 = e;
    int i2 = (i1 == 0) ? 1 : 0;
    #pragma unroll
    for (int e = 0; e < 4; e++) if (e != i1 && g[e] > g[i2]) i2 = e;
    float sm = g[i1] + g[i2]; if (sm < 1e-9f) sm = 1e-9f;
    int s1 = atomicAdd(&cnt[i1], 1);
    list[i1 * TKN + s1] = t0; wl[i1 * TKN + s1] = g[i1] / sm;
    int s2 = atomicAdd(&cnt[i2], 1);
    list[i2 * TKN + s2] = t0; wl[i2 * TKN + s2] = g[i2] / sm;
    /* gate-mean sums: warp-reduce then one atomic per warp per expert */
    #pragma unroll
    for (int e = 0; e < 4; e++) {
        float v = g[e];
        #pragma unroll
        for (int o = 16; o > 0; o >>= 1) v += __shfl_xor_sync(0xffffffffu, v, o);
        if ((threadIdx.x & 31) == 0) atomicAdd(&aux[e], v);
    }
}

__global__ void aux_kernel(const float* __restrict__ sums, const int* __restrict__ cnt,
                           float* __restrict__ out, long long pos) {
    float a = 0.f;
    #pragma unroll
    for (int e = 0; e < 4; e++)
        a += (sums[e] / (float)TKN) * ((float)cnt[e] / (float)TKN);
    out[pos] = (float)NE * a;
}

/* ---------------- final: out = xs + dwconv5(Tr) + tb ------------------ */
__global__ void final_kernel(const float* __restrict__ xs, const float* __restrict__ Tr,
                             const float* __restrict__ tw, const float* __restrict__ tb,
                             float* __restrict__ out) {
    int d = blockIdx.x * 256 + threadIdx.x;
    int n = blockIdx.y, b = blockIdx.z;
    long long idx = ((long long)b * SEQ + n) * DM + d;
    float acc = tb[d];
    #pragma unroll
    for (int t = 0; t < 5; t++) {
        int src = n + t - 2;
        if (src >= 0 && src < SEQ)
            acc += Tr[((long long)b * SEQ + src) * DM + d] * tw[d * 5 + t];
    }
    out[idx] = xs[idx] + acc;
}

/* ------------------------------- host --------------------------------- */
static void launch_gemm(bool bt, const float* A, const float* B, const float* bias,
                        const float* resid, const float* rowScale, int rsStride,
                        const int* rowIdx, const int* cntP,
                        float* C, int M, int N, int K,
                        long long sA, long long sB, long long sC, int batch, int flags) {
    dim3 grid((N + 127) / 128, (M + 127) / 128, batch);
    if (bt)
        gemm_tc<true><<<grid, 256, GEMM_SMEM>>>(A, B, bias, resid, rowScale, rsStride,
                                                rowIdx, cntP, C, M, N, K, sA, sB, sC, flags);
    else
        gemm_tc<false><<<grid, 256, GEMM_SMEM>>>(A, B, bias, resid, rowScale, rsStride,
                                                 rowIdx, cntP, C, M, N, K, sA, sB, sC, flags);
}

extern "C" void kernel_launch(void* const* d_in, const int* in_sizes, int n_in,
                              void* d_out, int out_size) {
    const float* x        = (const float*)d_in[0];
    const float* qw       = (const float*)d_in[1];
    const float* qb       = (const float*)d_in[2];
    const float* kw       = (const float*)d_in[3];
    const float* kb       = (const float*)d_in[4];
    const float* vw       = (const float*)d_in[5];
    const float* vb       = (const float*)d_in[6];
    const float* ow       = (const float*)d_in[7];
    const float* ob       = (const float*)d_in[8];
    const float* n1g      = (const float*)d_in[9];
    const float* n1b      = (const float*)d_in[10];
    const float* n2g      = (const float*)d_in[11];
    const float* n2b      = (const float*)d_in[12];
    const float* alpha    = (const float*)d_in[13];
    const float* dw7      = (const float*)d_in[14];
    const float* dw25     = (const float*)d_in[15];
    const float* dw49     = (const float*)d_in[16];
    const float* router_w = (const float*)d_in[17];
    const float* ew1      = (const float*)d_in[18];
    const float* eb1      = (const float*)d_in[19];
    const float* ew2      = (const float*)d_in[20];
    const float* eb2      = (const float*)d_in[21];
    const float* tw       = (const float*)d_in[22];
    const float* tb       = (const float*)d_in[23];
    float* out = (float*)d_out;

    cudaFuncSetAttribute(gemm_tc<true>,  cudaFuncAttributeMaxDynamicSharedMemorySize, GEMM_SMEM);
    cudaFuncSetAttribute(gemm_tc<false>, cudaFuncAttributeMaxDynamicSharedMemorySize, GEMM_SMEM);

    float *pTr, *pS, *pSn, *pq, *pk, *pv, *patt, *py, *pyt, *pxs, *pxf, *pg, *ph, *paux, *pwl;
    int *pcnt, *plist;
    cudaGetSymbolAddress((void**)&pTr,  g_Tr);
    cudaGetSymbolAddress((void**)&pS,   g_S);
    cudaGetSymbolAddress((void**)&pSn,  g_Sn);
    cudaGetSymbolAddress((void**)&pq,   g_q);
    cudaGetSymbolAddress((void**)&pk,   g_k);
    cudaGetSymbolAddress((void**)&pv,   g_v);
    cudaGetSymbolAddress((void**)&patt, g_att);
    cudaGetSymbolAddress((void**)&py,   g_y);
    cudaGetSymbolAddress((void**)&pyt,  g_yt);
    cudaGetSymbolAddress((void**)&pxs,  g_xs);
    cudaGetSymbolAddress((void**)&pxf,  g_xf);
    cudaGetSymbolAddress((void**)&pg,   g_gates);
    cudaGetSymbolAddress((void**)&ph,   g_hbuf);
    cudaGetSymbolAddress((void**)&paux, g_aux);
    cudaGetSymbolAddress((void**)&pwl,  g_wl);
    cudaGetSymbolAddress((void**)&pcnt, g_cnt);
    cudaGetSymbolAddress((void**)&plist, g_list);

    /* 1. decomposition: Tr, S */
    trend_kernel<<<dim3(DM / 256, SEQ, BB), 256>>>(x, dw7, dw25, dw49, alpha, pTr, pS);
    /* 2. Sn = LN(S) */
    ln_kernel<<<TKN, 256>>>(pS, pSn, n1g, n1b);
    /* 3. q,k,v projections -> [b,h,n,d] */
    launch_gemm(true, pSn, qw, qb, nullptr, nullptr, 0, nullptr, nullptr,
                pq, TKN, DM, DM, 0, 0, 0, 1, FLAG_PERM);
    launch_gemm(true, pSn, kw, kb, nullptr, nullptr, 0, nullptr, nullptr,
                pk, TKN, DM, DM, 0, 0, 0, 1, FLAG_PERM);
    launch_gemm(true, pSn, vw, vb, nullptr, nullptr, 0, nullptr, nullptr,
                pv, TKN, DM, DM, 0, 0, 0, 1, FLAG_PERM);
    /* 4. logits = q @ k^T (batched over 128 (b,h)) */
    launch_gemm(true, pq, pk, nullptr, nullptr, nullptr, 0, nullptr, nullptr, patt,
                SEQ, SEQ, HD, (long long)SEQ * HD, (long long)SEQ * HD,
                (long long)SEQ * SEQ, BB * NH, 0);
    /* 5. scale + ALiBi + softmax (in place) */
    softmax_alibi_kernel<<<dim3(SEQ, BB * NH), 256>>>(patt);
    /* 6. y = probs @ v */
    launch_gemm(false, patt, pv, nullptr, nullptr, nullptr, 0, nullptr, nullptr, py,
                SEQ, HD, SEQ, (long long)SEQ * SEQ, (long long)SEQ * HD,
                (long long)SEQ * HD, BB * NH, 0);
    /* 7. permute back, O projection with residual S -> xs */
    permute_y_kernel<<<(TKN * DM) / 256, 256>>>(py, pyt);
    launch_gemm(true, pyt, ow, ob, pS, nullptr, 0, nullptr, nullptr,
                pxs, TKN, DM, DM, 0, 0, 0, 1, 0);
    /* 8. MoE input LN */
    ln_kernel<<<TKN, 256>>>(pxs, pxf, n2g, n2b);
    /* 9. router logits, top-2 gating + gather lists + aux sums */
    launch_gemm(true, pxf, router_w, nullptr, nullptr, nullptr, 0, nullptr, nullptr,
                pg, TKN, NE, DM, 0, 0, 0, 1, 0);
    zero_aux_kernel<<<1, 32>>>(paux, pcnt);
    topk_kernel<<<TKN / 256, 256>>>(pg, pcnt, plist, pwl, paux);
    /* 10. experts: sparse token gather -> GEMM1(GELU) -> GEMM2 scatter+acc */
    for (int e = 0; e < NE; e++) {
        launch_gemm(true, pxf, ew1 + (long long)e * MH * DM, eb1 + e * MH,
                    nullptr, nullptr, 0, plist + e * TKN, pcnt + e,
                    ph, TKN, MH, DM, 0, 0, 0, 1, FLAG_GELU | FLAG_GATHER);
        launch_gemm(true, ph, ew2 + (long long)e * DM * MH, eb2 + e * DM,
                    nullptr, pwl + e * TKN, 1, plist + e * TKN, pcnt + e,
                    pxs, TKN, DM, MH, 0, 0, 0, 1, FLAG_ACCUM | FLAG_SCATTER);
    }
    /* 11. final: xs + trend conv, plus aux scalar */
    final_kernel<<<dim3(DM / 256, SEQ, BB), 256>>>(pxs, pTr, tw, tb, out);
    if (out_size > TKN * DM)
        aux_kernel<<<1, 1>>>(paux, pcnt, out, (long long)TKN * DM);
}

// round 10
// speedup vs baseline: 1.1393x; 1.1393x over previous
#include <cuda_runtime.h>
#include <math.h>
#include <stdint.h>

#define DM   1024
#define SEQ  1024
#define BB   8
#define NH   16
#define HD   64
#define TKN  (BB*SEQ)      /* 8192 tokens */
#define MH   2048
#define NE   4

/* ------------------------------ scratch ------------------------------ */
__device__ float g_Tr[BB*SEQ*DM];
__device__ float g_S [BB*SEQ*DM];
__device__ float g_Sn[BB*SEQ*DM];
__device__ float g_q [BB*NH*SEQ*HD];
__device__ float g_k [BB*NH*SEQ*HD];
__device__ float g_v [BB*NH*SEQ*HD];
__device__ float g_att[(long long)BB*NH*SEQ*SEQ];   /* 512 MB */
__device__ float g_y [BB*NH*SEQ*HD];
__device__ float g_yt[TKN*DM];
__device__ float g_xs[TKN*DM];
__device__ float g_xf[TKN*DM];
__device__ float g_gates[TKN*NE];
__device__ float g_hbuf[TKN*MH];         /* 64 MB */
__device__ float g_aux[8];
__device__ int   g_cnt[NE];
__device__ int   g_list[NE*TKN];
__device__ float g_wl[NE*TKN];
/* tf32-pre-rounded weights */
__device__ float g_wq[DM*DM];
__device__ float g_wk[DM*DM];
__device__ float g_wv[DM*DM];
__device__ float g_wo[DM*DM];
__device__ float g_wr[NE*DM];
__device__ float g_we1[NE*MH*DM];
__device__ float g_we2[NE*DM*MH];

__device__ __forceinline__ uint32_t f2tf(float f) {
    uint32_t u;
    asm("cvt.rna.tf32.f32 %0, %1;" : "=r"(u) : "f"(f));
    return u;
}
__device__ __forceinline__ float roundtf(float f) { return __uint_as_float(f2tf(f)); }

/* round-copy: dst = tf32_rna(src), vectorized */
__global__ void round_copy_kernel(const float* __restrict__ src, float* __restrict__ dst, int n4) {
    int i = blockIdx.x * 256 + threadIdx.x;
    if (i >= n4) return;
    float4 v = ((const float4*)src)[i];
    v.x = roundtf(v.x); v.y = roundtf(v.y); v.z = roundtf(v.z); v.w = roundtf(v.w);
    ((float4*)dst)[i] = v;
}

/* --------------------------- reductions ------------------------------ */
__device__ __forceinline__ float blockSum(float v, float* sh) {
    #pragma unroll
    for (int o = 16; o > 0; o >>= 1) v += __shfl_xor_sync(0xffffffffu, v, o);
    int w = threadIdx.x >> 5, l = threadIdx.x & 31;
    __syncthreads();
    if (l == 0) sh[w] = v;
    __syncthreads();
    int nw = blockDim.x >> 5;
    if (w == 0) {
        float x = (l < nw) ? sh[l] : 0.f;
        #pragma unroll
        for (int o = 4; o > 0; o >>= 1) x += __shfl_xor_sync(0xffffffffu, x, o);
        if (l == 0) sh[0] = x;
    }
    __syncthreads();
    return sh[0];
}

__device__ __forceinline__ float blockMax(float v, float* sh) {
    #pragma unroll
    for (int o = 16; o > 0; o >>= 1) v = fmaxf(v, __shfl_xor_sync(0xffffffffu, v, o));
    int w = threadIdx.x >> 5, l = threadIdx.x & 31;
    __syncthreads();
    if (l == 0) sh[w] = v;
    __syncthreads();
    int nw = blockDim.x >> 5;
    if (w == 0) {
        float x = (l < nw) ? sh[l] : -1e30f;
        #pragma unroll
        for (int o = 4; o > 0; o >>= 1) x = fmaxf(x, __shfl_xor_sync(0xffffffffu, x, o));
        if (l == 0) sh[0] = x;
    }
    __syncthreads();
    return sh[0];
}

/* ------------------------- trend decomposition ----------------------- */
__global__ void trend_kernel(const float* __restrict__ x,
                             const float* __restrict__ dw7,
                             const float* __restrict__ dw25,
                             const float* __restrict__ dw49,
                             const float* __restrict__ alpha,
                             float* __restrict__ Tr, float* __restrict__ S) {
    int d = blockIdx.x * 256 + threadIdx.x;
    int n = blockIdx.y, b = blockIdx.z;
    float a0 = alpha[0], a1 = alpha[1], a2 = alpha[2];
    float mx = fmaxf(a0, fmaxf(a1, a2));
    float e0 = expf(a0 - mx), e1 = expf(a1 - mx), e2 = expf(a2 - mx);
    float inv = 1.f / (e0 + e1 + e2);
    float w0 = e0 * inv, w1 = e1 * inv, w2 = e2 * inv;

    const float* xc = x + ((long long)b * SEQ) * DM + d;
    float t7 = 0.f, t25 = 0.f, t49 = 0.f, center = 0.f;
    #pragma unroll
    for (int o = -24; o <= 24; o++) {
        int src = n + o;
        if (src < 0) src = -src;
        else if (src >= SEQ) src = 2 * SEQ - 2 - src;
        float v = xc[(long long)src * DM];
        if (o == 0) center = v;
        t49 += v * dw49[d * 49 + (o + 24)];
        if (o >= -12 && o <= 12) t25 += v * dw25[d * 25 + (o + 12)];
        if (o >= -3  && o <= 3 ) t7  += v * dw7 [d * 7  + (o + 3)];
    }
    float tr = w0 * t7 + w1 * t25 + w2 * t49;
    long long idx = ((long long)b * SEQ + n) * DM + d;
    Tr[idx] = tr;
    S[idx]  = center - tr;
}

/* ------------------------------ LayerNorm ---------------------------- */
/* doRound: output pre-rounded to tf32 (it is consumed only as a GEMM A operand) */
__global__ void ln_kernel(const float* __restrict__ in, float* __restrict__ out,
                          const float* __restrict__ g, const float* __restrict__ b,
                          int doRound) {
    __shared__ float sh[32];
    long long row = blockIdx.x;
    const float* xr = in + row * DM;
    float* orow = out + row * DM;
    int t = threadIdx.x;
    float v[4]; float s = 0.f, sq = 0.f;
    #pragma unroll
    for (int a = 0; a < 4; a++) {
        int j = t + a * 256;
        v[a] = xr[j]; s += v[a]; sq += v[a] * v[a];
    }
    s  = blockSum(s,  sh);
    sq = blockSum(sq, sh);
    float mean = s * (1.f / DM);
    float var  = sq * (1.f / DM) - mean * mean;
    float rstd = rsqrtf(var + 1e-5f);
    #pragma unroll
    for (int a = 0; a < 4; a++) {
        int j = t + a * 256;
        float o = (v[a] - mean) * rstd * g[j] + b[j];
        orow[j] = doRound ? roundtf(o) : o;
    }
}

/* --------------------------- TF32 tensor GEMM ------------------------- */
/* C[M,N] = A[M,K] @ (BT ? B[N,K]^T : B[K,N]) with fused epilogue.
 * All operands must already be tf32-rounded fp32 (raw bits fed to mma).
 * 128x128x32 CTA tile, 256 threads = 8 warps, warp tile 64x32,
 * mma.sync.m16n8k8.tf32, cp.async 2-stage.
 * Optional token gather (A rows) / scatter (C rows) for sparse MoE. */
enum { FLAG_GELU = 1, FLAG_ACCUM = 2, FLAG_PERM = 4, FLAG_GATHER = 8,
       FLAG_SCATTER = 16, FLAG_ROUND = 32 };

#define AST 36     /* padded stride of A / BT-B smem rows (floats) */
#define BNN 132    /* padded stride of NN-B smem rows (floats) */
#define ABUF 4608  /* 128*36 floats, >= 32*132 = 4224 too */
#define GEMM_SMEM (4 * ABUF * 4 + 512)

__device__ __forceinline__ void cpa16(float* dst, const float* src, bool pred) {
    uint32_t d = (uint32_t)__cvta_generic_to_shared(dst);
    int sz = pred ? 16 : 0;
    asm volatile("cp.async.cg.shared.global [%0], [%1], 16, %2;"
                 :: "r"(d), "l"(src), "r"(sz));
}

#define MMA8(d, av, bv) \
    asm volatile("mma.sync.aligned.m16n8k8.row.col.f32.tf32.tf32.f32 " \
        "{%0,%1,%2,%3},{%4,%5,%6,%7},{%8,%9},{%0,%1,%2,%3};" \
        : "+f"((d)[0]), "+f"((d)[1]), "+f"((d)[2]), "+f"((d)[3]) \
        : "r"((av)[0]), "r"((av)[1]), "r"((av)[2]), "r"((av)[3]), \
          "r"((bv)[0]), "r"((bv)[1]))

template<bool BT>
__global__ __launch_bounds__(256) void gemm_tc(
    const float* __restrict__ A, const float* __restrict__ Bm,
    const float* __restrict__ bias, const float* __restrict__ resid,
    const float* __restrict__ rowScale, int rsStride,
    const int* __restrict__ rowIdx, const int* __restrict__ cntP,
    float* __restrict__ C, int M, int N, int K,
    long long sA, long long sB, long long sC, int flags) {
    extern __shared__ float sm[];
    float* As = sm;              /* 2 x ABUF */
    float* Bs = sm + 2 * ABUF;   /* 2 x ABUF */
    int*   ridx = (int*)(sm + 4 * ABUF);  /* 128 ints: global A-row per tile row */
    int z = blockIdx.z;
    A  += (long long)z * sA;
    Bm += (long long)z * sB;
    C  += (long long)z * sC;
    int m0 = blockIdx.y * 128, n0 = blockIdx.x * 128;
    int cntV = cntP ? cntP[0] : M;
    if (m0 >= cntV) return;
    int tid = threadIdx.x;
    int lane = tid & 31, warp = tid >> 5;
    int wm = (warp & 1) * 64;
    int wn = (warp >> 1) * 32;
    int g = lane >> 2, qd = lane & 3;

    if (flags & FLAG_GATHER) {
        if (tid < 128) {
            int s = m0 + tid; if (s >= cntV) s = cntV - 1;
            ridx[tid] = rowIdx[s];
        }
    } else {
        if (tid < 128) ridx[tid] = m0 + tid;
    }
    __syncthreads();

    float acc[4][4][4];
    #pragma unroll
    for (int i = 0; i < 4; i++)
        #pragma unroll
        for (int j = 0; j < 4; j++)
            #pragma unroll
            for (int l = 0; l < 4; l++) acc[i][j][l] = 0.f;

    auto prefetch = [&](int kt, int buf) {
        int k0 = kt * 32;
        float* as = As + buf * ABUF;
        float* bs = Bs + buf * ABUF;
        #pragma unroll
        for (int i = 0; i < 4; i++) {
            int c = tid + i * 256;          /* 0..1023 */
            int row = c >> 3, cc = (c & 7) * 4;
            cpa16(&as[row * AST + cc], A + (long long)ridx[row] * K + k0 + cc, true);
        }
        if (BT) {
            #pragma unroll
            for (int i = 0; i < 4; i++) {
                int c = tid + i * 256;
                int row = c >> 3, cc = (c & 7) * 4;
                bool p = (n0 + row) < N;
                const float* src = p ? (Bm + (long long)(n0 + row) * K + k0 + cc) : Bm;
                cpa16(&bs[row * AST + cc], src, p);
            }
        } else {
            #pragma unroll
            for (int i = 0; i < 4; i++) {
                int c = tid + i * 256;
                int row = c >> 5, cc = (c & 31) * 4;
                bool p = (n0 + cc) < N;
                const float* src = p ? (Bm + (long long)(k0 + row) * N + n0 + cc) : Bm;
                cpa16(&bs[row * BNN + cc], src, p);
            }
        }
    };

    const int KT = K / 32;
    prefetch(0, 0);
    asm volatile("cp.async.commit_group;");
    for (int kt = 0; kt < KT; kt++) {
        if (kt + 1 < KT) {
            prefetch(kt + 1, (kt + 1) & 1);
            asm volatile("cp.async.commit_group;");
            asm volatile("cp.async.wait_group 1;");
        } else {
            asm volatile("cp.async.wait_group 0;");
        }
        __syncthreads();
        const uint32_t* as = (const uint32_t*)(As + (kt & 1) * ABUF);
        const uint32_t* bs = (const uint32_t*)(Bs + (kt & 1) * ABUF);
        #pragma unroll
        for (int ks = 0; ks < 4; ks++) {
            int k8 = ks * 8;
            uint32_t a[4][4], b[4][2];
            #pragma unroll
            for (int mi = 0; mi < 4; mi++) {
                int r = wm + mi * 16 + g;
                a[mi][0] = as[r * AST + k8 + qd];
                a[mi][1] = as[(r + 8) * AST + k8 + qd];
                a[mi][2] = as[r * AST + k8 + qd + 4];
                a[mi][3] = as[(r + 8) * AST + k8 + qd + 4];
            }
            #pragma unroll
            for (int ni = 0; ni < 4; ni++) {
                int cn = wn + ni * 8 + g;
                if (BT) {
                    b[ni][0] = bs[cn * AST + k8 + qd];
                    b[ni][1] = bs[cn * AST + k8 + qd + 4];
                } else {
                    b[ni][0] = bs[(k8 + qd) * BNN + cn];
                    b[ni][1] = bs[(k8 + qd + 4) * BNN + cn];
                }
            }
            #pragma unroll
            for (int mi = 0; mi < 4; mi++)
                #pragma unroll
                for (int ni = 0; ni < 4; ni++)
                    MMA8(acc[mi][ni], a[mi], b[ni]);
        }
        __syncthreads();
    }

    auto epi = [&](int m, int n, float v) {
        if (n >= N) return;
        if ((flags & FLAG_SCATTER) && m >= cntV) return;
        if (bias) v += bias[n];
        if (flags & FLAG_GELU) v = 0.5f * v * (1.f + erff(v * 0.70710678118654752f));
        if (rowScale) v *= rowScale[(long long)m * rsStride];
        int om = (flags & FLAG_SCATTER) ? rowIdx[m] : m;
        if (resid) v += resid[(long long)om * N + n];
        if (flags & FLAG_ROUND) v = roundtf(v);
        long long idx;
        if (flags & FLAG_PERM) {
            int b_ = om >> 10, ns = om & 1023, h = n >> 6, d = n & 63;
            idx = ((long long)(b_ * NH + h) * SEQ + ns) * HD + d;
        } else {
            idx = (long long)om * N + n;
        }
        if (flags & FLAG_ACCUM) C[idx] += v; else C[idx] = v;
    };

    #pragma unroll
    for (int mi = 0; mi < 4; mi++)
        #pragma unroll
        for (int ni = 0; ni < 4; ni++) {
            int m = m0 + wm + mi * 16 + g;
            int n = n0 + wn + ni * 8 + qd * 2;
            float* c4 = acc[mi][ni];
            epi(m,     n,     c4[0]);
            epi(m,     n + 1, c4[1]);
            epi(m + 8, n,     c4[2]);
            epi(m + 8, n + 1, c4[3]);
        }
}

/* ------------------------- ALiBi softmax ------------------------------ */
/* writes tf32-rounded probabilities (consumed only as GEMM A operand) */
__global__ void softmax_alibi_kernel(float* __restrict__ att) {
    __shared__ float sh[32];
    int i = blockIdx.x;
    int bh = blockIdx.y;
    int h = bh & (NH - 1);
    float slope = exp2f(-0.5f * (float)(h + 1));
    float* row = att + ((long long)bh * SEQ + i) * SEQ;
    int t = threadIdx.x;
    float v[4]; float mx = -1e30f;
    #pragma unroll
    for (int a = 0; a < 4; a++) {
        int j = t + a * 256;
        float dist = (j > i) ? (float)(j - i) : 0.f;
        v[a] = row[j] * 0.125f - slope * dist;
        mx = fmaxf(mx, v[a]);
    }
    mx = blockMax(mx, sh);
    float s = 0.f;
    #pragma unroll
    for (int a = 0; a < 4; a++) { v[a] = expf(v[a] - mx); s += v[a]; }
    s = blockSum(s, sh);
    float inv = 1.f / s;
    #pragma unroll
    for (int a = 0; a < 4; a++) row[t + a * 256] = roundtf(v[a] * inv);
}

/* ---------------- attention output permute [b,h,n,d]->[b,n,D] --------- */
/* rounds to tf32 (output consumed only as GEMM A operand) */
__global__ void permute_y_kernel(const float* __restrict__ y, float* __restrict__ out) {
    long long idx = (long long)blockIdx.x * 256 + threadIdx.x;
    int dfull = (int)(idx & 1023);
    int n = (int)((idx >> 10) & 1023);
    int b = (int)(idx >> 20);
    int h = dfull >> 6, d = dfull & 63;
    out[idx] = roundtf(y[((long long)(b * NH + h) * SEQ + n) * HD + d]);
}

/* ------------------- router top-2, gather lists, aux ------------------ */
__global__ void zero_aux_kernel(float* a, int* c) {
    if (threadIdx.x < 8) a[threadIdx.x] = 0.f;
    if (threadIdx.x < NE) c[threadIdx.x] = 0;
}

__global__ void topk_kernel(const float* __restrict__ gl,
                            int* __restrict__ cnt, int* __restrict__ list,
                            float* __restrict__ wl, float* __restrict__ aux) {
    int t0 = blockIdx.x * blockDim.x + threadIdx.x;
    float g[4];
    #pragma unroll
    for (int e = 0; e < 4; e++) g[e] = gl[t0 * 4 + e];
    float mx = fmaxf(fmaxf(g[0], g[1]), fmaxf(g[2], g[3]));
    float s = 0.f;
    #pragma unroll
    for (int e = 0; e < 4; e++) { g[e] = expf(g[e] - mx); s += g[e]; }
    float inv = 1.f / s;
    #pragma unroll
    for (int e = 0; e < 4; e++) g[e] *= inv;
    int i1 = 0;
    #pragma unroll
    for (int e = 1; e < 4; e++) if (g[e] > g[i1]) i1 = e;
    int i2 = (i1 == 0) ? 1 : 0;
    #pragma unroll
    for (int e = 0; e < 4; e++) if (e != i1 && g[e] > g[i2]) i2 = e;
    float sm = g[i1] + g[i2]; if (sm < 1e-9f) sm = 1e-9f;
    int s1 = atomicAdd(&cnt[i1], 1);
    list[i1 * TKN + s1] = t0; wl[i1 * TKN + s1] = g[i1] / sm;
    int s2 = atomicAdd(&cnt[i2], 1);
    list[i2 * TKN + s2] = t0; wl[i2 * TKN + s2] = g[i2] / sm;
    /* gate-mean sums: warp-reduce then one atomic per warp per expert */
    #pragma unroll
    for (int e = 0; e < 4; e++) {
        float v = g[e];
        #pragma unroll
        for (int o = 16; o > 0; o >>= 1) v += __shfl_xor_sync(0xffffffffu, v, o);
        if ((threadIdx.x & 31) == 0) atomicAdd(&aux[e], v);
    }
}

__global__ void aux_kernel(const float* __restrict__ sums, const int* __restrict__ cnt,
                           float* __restrict__ out, long long pos) {
    float a = 0.f;
    #pragma unroll
    for (int e = 0; e < 4; e++)
        a += (sums[e] / (float)TKN) * ((float)cnt[e] / (float)TKN);
    out[pos] = (float)NE * a;
}

/* ---------------- final: out = xs + dwconv5(Tr) + tb ------------------ */
__global__ void final_kernel(const float* __restrict__ xs, const float* __restrict__ Tr,
                             const float* __restrict__ tw, const float* __restrict__ tb,
                             float* __restrict__ out) {
    int d = blockIdx.x * 256 + threadIdx.x;
    int n = blockIdx.y, b = blockIdx.z;
    long long idx = ((long long)b * SEQ + n) * DM + d;
    float acc = tb[d];
    #pragma unroll
    for (int t = 0; t < 5; t++) {
        int src = n + t - 2;
        if (src >= 0 && src < SEQ)
            acc += Tr[((long long)b * SEQ + src) * DM + d] * tw[d * 5 + t];
    }
    out[idx] = xs[idx] + acc;
}

/* ------------------------------- host --------------------------------- */
static void launch_gemm(bool bt, const float* A, const float* B, const float* bias,
                        const float* resid, const float* rowScale, int rsStride,
                        const int* rowIdx, const int* cntP,
                        float* C, int M, int N, int K,
                        long long sA, long long sB, long long sC, int batch, int flags) {
    dim3 grid((N + 127) / 128, (M + 127) / 128, batch);
    if (bt)
        gemm_tc<true><<<grid, 256, GEMM_SMEM>>>(A, B, bias, resid, rowScale, rsStride,
                                                rowIdx, cntP, C, M, N, K, sA, sB, sC, flags);
    else
        gemm_tc<false><<<grid, 256, GEMM_SMEM>>>(A, B, bias, resid, rowScale, rsStride,
                                                 rowIdx, cntP, C, M, N, K, sA, sB, sC, flags);
}

static void round_copy(const float* src, float* dst, long long n) {
    int n4 = (int)(n / 4);
    round_copy_kernel<<<(n4 + 255) / 256, 256>>>(src, dst, n4);
}

extern "C" void kernel_launch(void* const* d_in, const int* in_sizes, int n_in,
                              void* d_out, int out_size) {
    const float* x        = (const float*)d_in[0];
    const float* qw       = (const float*)d_in[1];
    const float* qb       = (const float*)d_in[2];
    const float* kw       = (const float*)d_in[3];
    const float* kb       = (const float*)d_in[4];
    const float* vw       = (const float*)d_in[5];
    const float* vb       = (const float*)d_in[6];
    const float* ow       = (const float*)d_in[7];
    const float* ob       = (const float*)d_in[8];
    const float* n1g      = (const float*)d_in[9];
    const float* n1b      = (const float*)d_in[10];
    const float* n2g      = (const float*)d_in[11];
    const float* n2b      = (const float*)d_in[12];
    const float* alpha    = (const float*)d_in[13];
    const float* dw7      = (const float*)d_in[14];
    const float* dw25     = (const float*)d_in[15];
    const float* dw49     = (const float*)d_in[16];
    const float* router_w = (const float*)d_in[17];
    const float* ew1      = (const float*)d_in[18];
    const float* eb1      = (const float*)d_in[19];
    const float* ew2      = (const float*)d_in[20];
    const float* eb2      = (const float*)d_in[21];
    const float* tw       = (const float*)d_in[22];
    const float* tb       = (const float*)d_in[23];
    float* out = (float*)d_out;

    cudaFuncSetAttribute(gemm_tc<true>,  cudaFuncAttributeMaxDynamicSharedMemorySize, GEMM_SMEM);
    cudaFuncSetAttribute(gemm_tc<false>, cudaFuncAttributeMaxDynamicSharedMemorySize, GEMM_SMEM);

    float *pTr, *pS, *pSn, *pq, *pk, *pv, *patt, *py, *pyt, *pxs, *pxf, *pg, *ph, *paux, *pwl;
    float *pwq, *pwk, *pwv, *pwo, *pwr, *pwe1, *pwe2;
    int *pcnt, *plist;
    cudaGetSymbolAddress((void**)&pTr,  g_Tr);
    cudaGetSymbolAddress((void**)&pS,   g_S);
    cudaGetSymbolAddress((void**)&pSn,  g_Sn);
    cudaGetSymbolAddress((void**)&pq,   g_q);
    cudaGetSymbolAddress((void**)&pk,   g_k);
    cudaGetSymbolAddress((void**)&pv,   g_v);
    cudaGetSymbolAddress((void**)&patt, g_att);
    cudaGetSymbolAddress((void**)&py,   g_y);
    cudaGetSymbolAddress((void**)&pyt,  g_yt);
    cudaGetSymbolAddress((void**)&pxs,  g_xs);
    cudaGetSymbolAddress((void**)&pxf,  g_xf);
    cudaGetSymbolAddress((void**)&pg,   g_gates);
    cudaGetSymbolAddress((void**)&ph,   g_hbuf);
    cudaGetSymbolAddress((void**)&paux, g_aux);
    cudaGetSymbolAddress((void**)&pwl,  g_wl);
    cudaGetSymbolAddress((void**)&pcnt, g_cnt);
    cudaGetSymbolAddress((void**)&plist, g_list);
    cudaGetSymbolAddress((void**)&pwq,  g_wq);
    cudaGetSymbolAddress((void**)&pwk,  g_wk);
    cudaGetSymbolAddress((void**)&pwv,  g_wv);
    cudaGetSymbolAddress((void**)&pwo,  g_wo);
    cudaGetSymbolAddress((void**)&pwr,  g_wr);
    cudaGetSymbolAddress((void**)&pwe1, g_we1);
    cudaGetSymbolAddress((void**)&pwe2, g_we2);

    /* 0. pre-round all GEMM weights to tf32 (once per replay, ~30us) */
    round_copy(qw, pwq, (long long)DM * DM);
    round_copy(kw, pwk, (long long)DM * DM);
    round_copy(vw, pwv, (long long)DM * DM);
    round_copy(ow, pwo, (long long)DM * DM);
    round_copy(router_w, pwr, (long long)NE * DM);
    round_copy(ew1, pwe1, (long long)NE * MH * DM);
    round_copy(ew2, pwe2, (long long)NE * DM * MH);

    /* 1. decomposition: Tr, S */
    trend_kernel<<<dim3(DM / 256, SEQ, BB), 256>>>(x, dw7, dw25, dw49, alpha, pTr, pS);
    /* 2. Sn = LN(S), tf32-rounded */
    ln_kernel<<<TKN, 256>>>(pS, pSn, n1g, n1b, 1);
    /* 3. q,k,v projections -> [b,h,n,d], outputs tf32-rounded */
    launch_gemm(true, pSn, pwq, qb, nullptr, nullptr, 0, nullptr, nullptr,
                pq, TKN, DM, DM, 0, 0, 0, 1, FLAG_PERM | FLAG_ROUND);
    launch_gemm(true, pSn, pwk, kb, nullptr, nullptr, 0, nullptr, nullptr,
                pk, TKN, DM, DM, 0, 0, 0, 1, FLAG_PERM | FLAG_ROUND);
    launch_gemm(true, pSn, pwv, vb, nullptr, nullptr, 0, nullptr, nullptr,
                pv, TKN, DM, DM, 0, 0, 0, 1, FLAG_PERM | FLAG_ROUND);
    /* 4. logits = q @ k^T (batched over 128 (b,h)) */
    launch_gemm(true, pq, pk, nullptr, nullptr, nullptr, 0, nullptr, nullptr, patt,
                SEQ, SEQ, HD, (long long)SEQ * HD, (long long)SEQ * HD,
                (long long)SEQ * SEQ, BB * NH, 0);
    /* 5. scale + ALiBi + softmax (in place, rounded) */
    softmax_alibi_kernel<<<dim3(SEQ, BB * NH), 256>>>(patt);
    /* 6. y = probs @ v */
    launch_gemm(false, patt, pv, nullptr, nullptr, nullptr, 0, nullptr, nullptr, py,
                SEQ, HD, SEQ, (long long)SEQ * SEQ, (long long)SEQ * HD,
                (long long)SEQ * HD, BB * NH, 0);
    /* 7. permute back (rounded), O projection with residual S -> xs */
    permute_y_kernel<<<(TKN * DM) / 256, 256>>>(py, pyt);
    launch_gemm(true, pyt, pwo, ob, pS, nullptr, 0, nullptr, nullptr,
                pxs, TKN, DM, DM, 0, 0, 0, 1, 0);
    /* 8. MoE input LN, tf32-rounded */
    ln_kernel<<<TKN, 256>>>(pxs, pxf, n2g, n2b, 1);
    /* 9. router logits, top-2 gating + gather lists + aux sums */
    launch_gemm(true, pxf, pwr, nullptr, nullptr, nullptr, 0, nullptr, nullptr,
                pg, TKN, NE, DM, 0, 0, 0, 1, 0);
    zero_aux_kernel<<<1, 32>>>(paux, pcnt);
    topk_kernel<<<TKN / 256, 256>>>(pg, pcnt, plist, pwl, paux);
    /* 10. experts: sparse token gather -> GEMM1(GELU, rounded h) -> GEMM2 scatter+acc */
    for (int e = 0; e < NE; e++) {
        launch_gemm(true, pxf, pwe1 + (long long)e * MH * DM, eb1 + e * MH,
                    nullptr, nullptr, 0, plist + e * TKN, pcnt + e,
                    ph, TKN, MH, DM, 0, 0, 0, 1, FLAG_GELU | FLAG_GATHER | FLAG_ROUND);
        launch_gemm(true, ph, pwe2 + (long long)e * DM * MH, eb2 + e * DM,
                    nullptr, pwl + e * TKN, 1, plist + e * TKN, pcnt + e,
                    pxs, TKN, DM, MH, 0, 0, 0, 1, FLAG_ACCUM | FLAG_SCATTER);
    }
    /* 11. final: xs + trend conv, plus aux scalar */
    final_kernel<<<dim3(DM / 256, SEQ, BB), 256>>>(pxs, pTr, tw, tb, out);
    if (out_size > TKN * DM)
        aux_kernel<<<1, 1>>>(paux, pcnt, out, (long long)TKN * DM);
}

// round 15
// speedup vs baseline: 1.4021x; 1.2307x over previous
#include <cuda_runtime.h>
#include <math.h>
#include <stdint.h>

#define DM   1024
#define SEQ  1024
#define BB   8
#define NH   16
#define HD   64
#define TKN  (BB*SEQ)      /* 8192 tokens */
#define MH   2048
#define NE   4

/* ------------------------------ scratch ------------------------------ */
__device__ float g_Tr[BB*SEQ*DM];
__device__ float g_S [BB*SEQ*DM];
__device__ float g_Sn[BB*SEQ*DM];
__device__ float g_q [BB*NH*SEQ*HD];
__device__ float g_k [BB*NH*SEQ*HD];
__device__ float g_vt[BB*NH*HD*SEQ];                /* V transposed [b,h,d,n] */
__device__ float g_att[(long long)BB*NH*SEQ*SEQ];   /* 512 MB */
__device__ float g_yt[TKN*DM];
__device__ float g_xs[TKN*DM];
__device__ float g_xf[TKN*DM];
__device__ float g_gates[TKN*NE];
__device__ float g_hbuf[TKN*MH];                    /* 64 MB */
__device__ float g_aux[8];
__device__ int   g_cnt[NE];
__device__ int   g_list[NE*TKN];
__device__ float g_wl[NE*TKN];
/* tf32-pre-rounded weights */
__device__ float g_wq[DM*DM];
__device__ float g_wk[DM*DM];
__device__ float g_wv[DM*DM];
__device__ float g_wo[DM*DM];
__device__ float g_wr[NE*DM];
__device__ float g_we1[NE*MH*DM];
__device__ float g_we2[NE*DM*MH];

__device__ __forceinline__ uint32_t f2tf(float f) {
    uint32_t u;
    asm("cvt.rna.tf32.f32 %0, %1;" : "=r"(u) : "f"(f));
    return u;
}
__device__ __forceinline__ float roundtf(float f) { return __uint_as_float(f2tf(f)); }

/* round-copy: dst = tf32_rna(src), vectorized */
__global__ void round_copy_kernel(const float* __restrict__ src, float* __restrict__ dst, int n4) {
    int i = blockIdx.x * 256 + threadIdx.x;
    if (i >= n4) return;
    float4 v = ((const float4*)src)[i];
    v.x = roundtf(v.x); v.y = roundtf(v.y); v.z = roundtf(v.z); v.w = roundtf(v.w);
    ((float4*)dst)[i] = v;
}

/* --------------------------- reductions ------------------------------ */
__device__ __forceinline__ float blockSum(float v, float* sh) {
    #pragma unroll
    for (int o = 16; o > 0; o >>= 1) v += __shfl_xor_sync(0xffffffffu, v, o);
    int w = threadIdx.x >> 5, l = threadIdx.x & 31;
    __syncthreads();
    if (l == 0) sh[w] = v;
    __syncthreads();
    int nw = blockDim.x >> 5;
    if (w == 0) {
        float x = (l < nw) ? sh[l] : 0.f;
        #pragma unroll
        for (int o = 4; o > 0; o >>= 1) x += __shfl_xor_sync(0xffffffffu, x, o);
        if (l == 0) sh[0] = x;
    }
    __syncthreads();
    return sh[0];
}

__device__ __forceinline__ float blockMax(float v, float* sh) {
    #pragma unroll
    for (int o = 16; o > 0; o >>= 1) v = fmaxf(v, __shfl_xor_sync(0xffffffffu, v, o));
    int w = threadIdx.x >> 5, l = threadIdx.x & 31;
    __syncthreads();
    if (l == 0) sh[w] = v;
    __syncthreads();
    int nw = blockDim.x >> 5;
    if (w == 0) {
        float x = (l < nw) ? sh[l] : -1e30f;
        #pragma unroll
        for (int o = 4; o > 0; o >>= 1) x = fmaxf(x, __shfl_xor_sync(0xffffffffu, x, o));
        if (l == 0) sh[0] = x;
    }
    __syncthreads();
    return sh[0];
}

/* ------------------------- trend decomposition ----------------------- */
__global__ void trend_kernel(const float* __restrict__ x,
                             const float* __restrict__ dw7,
                             const float* __restrict__ dw25,
                             const float* __restrict__ dw49,
                             const float* __restrict__ alpha,
                             float* __restrict__ Tr, float* __restrict__ S) {
    int d = blockIdx.x * 256 + threadIdx.x;
    int n = blockIdx.y, b = blockIdx.z;
    float a0 = alpha[0], a1 = alpha[1], a2 = alpha[2];
    float mx = fmaxf(a0, fmaxf(a1, a2));
    float e0 = expf(a0 - mx), e1 = expf(a1 - mx), e2 = expf(a2 - mx);
    float inv = 1.f / (e0 + e1 + e2);
    float w0 = e0 * inv, w1 = e1 * inv, w2 = e2 * inv;

    const float* xc = x + ((long long)b * SEQ) * DM + d;
    float t7 = 0.f, t25 = 0.f, t49 = 0.f, center = 0.f;
    #pragma unroll
    for (int o = -24; o <= 24; o++) {
        int src = n + o;
        if (src < 0) src = -src;
        else if (src >= SEQ) src = 2 * SEQ - 2 - src;
        float v = xc[(long long)src * DM];
        if (o == 0) center = v;
        t49 += v * dw49[d * 49 + (o + 24)];
        if (o >= -12 && o <= 12) t25 += v * dw25[d * 25 + (o + 12)];
        if (o >= -3  && o <= 3 ) t7  += v * dw7 [d * 7  + (o + 3)];
    }
    float tr = w0 * t7 + w1 * t25 + w2 * t49;
    long long idx = ((long long)b * SEQ + n) * DM + d;
    Tr[idx] = tr;
    S[idx]  = center - tr;
}

/* ------------------------------ LayerNorm ---------------------------- */
__global__ void ln_kernel(const float* __restrict__ in, float* __restrict__ out,
                          const float* __restrict__ g, const float* __restrict__ b,
                          int doRound) {
    __shared__ float sh[32];
    long long row = blockIdx.x;
    const float* xr = in + row * DM;
    float* orow = out + row * DM;
    int t = threadIdx.x;
    float v[4]; float s = 0.f, sq = 0.f;
    #pragma unroll
    for (int a = 0; a < 4; a++) {
        int j = t + a * 256;
        v[a] = xr[j]; s += v[a]; sq += v[a] * v[a];
    }
    s  = blockSum(s,  sh);
    sq = blockSum(sq, sh);
    float mean = s * (1.f / DM);
    float var  = sq * (1.f / DM) - mean * mean;
    float rstd = rsqrtf(var + 1e-5f);
    #pragma unroll
    for (int a = 0; a < 4; a++) {
        int j = t + a * 256;
        float o = (v[a] - mean) * rstd * g[j] + b[j];
        orow[j] = doRound ? roundtf(o) : o;
    }
}

/* --------------------------- TF32 tensor GEMM ------------------------- */
/* C[M,N] = A[M,K] @ B[N,K]^T (BT form only) with fused epilogue.
 * Operands must be pre-rounded tf32 fp32 (raw bits -> mma).
 * 128x128x32 CTA tile, 8 warps, warp 64x32, m16n8k8.tf32, cp.async 2-stage,
 * __launch_bounds__(256,2) for 2 CTAs/SM. */
enum { FLAG_GELU = 1, FLAG_ACCUM = 2, FLAG_PERM = 4, FLAG_GATHER = 8,
       FLAG_SCATTER = 16, FLAG_ROUND = 32, FLAG_PERMT = 64, FLAG_PERMY = 128 };

#define AST 36     /* padded stride of smem rows (floats) */
#define ABUF 4608  /* 128*36 floats per stage */
#define GEMM_SMEM (4 * ABUF * 4 + 512)

__device__ __forceinline__ void cpa16(float* dst, const float* src, bool pred) {
    uint32_t d = (uint32_t)__cvta_generic_to_shared(dst);
    int sz = pred ? 16 : 0;
    asm volatile("cp.async.cg.shared.global [%0], [%1], 16, %2;"
                 :: "r"(d), "l"(src), "r"(sz));
}

#define MMA8(d, av, bv) \
    asm volatile("mma.sync.aligned.m16n8k8.row.col.f32.tf32.tf32.f32 " \
        "{%0,%1,%2,%3},{%4,%5,%6,%7},{%8,%9},{%0,%1,%2,%3};" \
        : "+f"((d)[0]), "+f"((d)[1]), "+f"((d)[2]), "+f"((d)[3]) \
        : "r"((av)[0]), "r"((av)[1]), "r"((av)[2]), "r"((av)[3]), \
          "r"((bv)[0]), "r"((bv)[1]))

__global__ __launch_bounds__(256, 2) void gemm_tc(
    const float* __restrict__ A, const float* __restrict__ Bm,
    const float* __restrict__ bias, const float* __restrict__ resid,
    const float* __restrict__ rowScale, int rsStride,
    const int* __restrict__ rowIdx, const int* __restrict__ cntP,
    float* __restrict__ C, int M, int N, int K,
    long long sA, long long sB, long long sC, int flags) {
    extern __shared__ float sm[];
    float* As = sm;              /* 2 x ABUF */
    float* Bs = sm + 2 * ABUF;   /* 2 x ABUF */
    int*   ridx = (int*)(sm + 4 * ABUF);
    int z = blockIdx.z;
    A  += (long long)z * sA;
    Bm += (long long)z * sB;
    C  += (long long)z * sC;
    int m0 = blockIdx.y * 128, n0 = blockIdx.x * 128;
    int cntV = cntP ? cntP[0] : M;
    if (m0 >= cntV) return;
    int tid = threadIdx.x;
    int lane = tid & 31, warp = tid >> 5;
    int wm = (warp & 1) * 64;
    int wn = (warp >> 1) * 32;
    int g = lane >> 2, qd = lane & 3;

    if (flags & FLAG_GATHER) {
        if (tid < 128) {
            int s = m0 + tid; if (s >= cntV) s = cntV - 1;
            ridx[tid] = rowIdx[s];
        }
    } else {
        if (tid < 128) ridx[tid] = m0 + tid;
    }
    __syncthreads();

    float acc[4][4][4];
    #pragma unroll
    for (int i = 0; i < 4; i++)
        #pragma unroll
        for (int j = 0; j < 4; j++)
            #pragma unroll
            for (int l = 0; l < 4; l++) acc[i][j][l] = 0.f;

    auto prefetch = [&](int kt, int buf) {
        int k0 = kt * 32;
        float* as = As + buf * ABUF;
        float* bs = Bs + buf * ABUF;
        #pragma unroll
        for (int i = 0; i < 4; i++) {
            int c = tid + i * 256;          /* 0..1023 */
            int row = c >> 3, cc = (c & 7) * 4;
            cpa16(&as[row * AST + cc], A + (long long)ridx[row] * K + k0 + cc, true);
        }
        #pragma unroll
        for (int i = 0; i < 4; i++) {
            int c = tid + i * 256;
            int row = c >> 3, cc = (c & 7) * 4;
            bool p = (n0 + row) < N;
            const float* src = p ? (Bm + (long long)(n0 + row) * K + k0 + cc) : Bm;
            cpa16(&bs[row * AST + cc], src, p);
        }
    };

    const int KT = K / 32;
    prefetch(0, 0);
    asm volatile("cp.async.commit_group;");
    for (int kt = 0; kt < KT; kt++) {
        if (kt + 1 < KT) {
            prefetch(kt + 1, (kt + 1) & 1);
            asm volatile("cp.async.commit_group;");
            asm volatile("cp.async.wait_group 1;");
        } else {
            asm volatile("cp.async.wait_group 0;");
        }
        __syncthreads();
        const uint32_t* as = (const uint32_t*)(As + (kt & 1) * ABUF);
        const uint32_t* bs = (const uint32_t*)(Bs + (kt & 1) * ABUF);
        #pragma unroll
        for (int ks = 0; ks < 4; ks++) {
            int k8 = ks * 8;
            uint32_t a[4][4], b[4][2];
            #pragma unroll
            for (int mi = 0; mi < 4; mi++) {
                int r = wm + mi * 16 + g;
                a[mi][0] = as[r * AST + k8 + qd];
                a[mi][1] = as[(r + 8) * AST + k8 + qd];
                a[mi][2] = as[r * AST + k8 + qd + 4];
                a[mi][3] = as[(r + 8) * AST + k8 + qd + 4];
            }
            #pragma unroll
            for (int ni = 0; ni < 4; ni++) {
                int cn = wn + ni * 8 + g;
                b[ni][0] = bs[cn * AST + k8 + qd];
                b[ni][1] = bs[cn * AST + k8 + qd + 4];
            }
            #pragma unroll
            for (int mi = 0; mi < 4; mi++)
                #pragma unroll
                for (int ni = 0; ni < 4; ni++)
                    MMA8(acc[mi][ni], a[mi], b[ni]);
        }
        __syncthreads();
    }

    auto epi = [&](int m, int n, float v) {
        if (n >= N) return;
        if ((flags & FLAG_SCATTER) && m >= cntV) return;
        if (bias) v += bias[n];
        if (flags & FLAG_GELU) v = 0.5f * v * (1.f + erff(v * 0.70710678118654752f));
        if (rowScale) v *= rowScale[(long long)m * rsStride];
        int om = (flags & FLAG_SCATTER) ? rowIdx[m] : m;
        if (resid) v += resid[(long long)om * N + n];
        if (flags & FLAG_ROUND) v = roundtf(v);
        long long idx;
        if (flags & FLAG_PERM) {
            int b_ = om >> 10, ns = om & 1023, h = n >> 6, d = n & 63;
            idx = ((long long)(b_ * NH + h) * SEQ + ns) * HD + d;
        } else if (flags & FLAG_PERMT) {
            int b_ = om >> 10, ns = om & 1023, h = n >> 6, d = n & 63;
            idx = ((long long)(b_ * NH + h) * HD + d) * SEQ + ns;
        } else if (flags & FLAG_PERMY) {
            /* batched over z=b*NH+h ; om=query ; n=head-dim ; C not pre-offset (sC=0) */
            idx = ((long long)(z >> 4) * SEQ + om) * DM + (z & 15) * HD + n;
        } else {
            idx = (long long)om * N + n;
        }
        if (flags & FLAG_ACCUM) C[idx] += v; else C[idx] = v;
    };

    #pragma unroll
    for (int mi = 0; mi < 4; mi++)
        #pragma unroll
        for (int ni = 0; ni < 4; ni++) {
            int m = m0 + wm + mi * 16 + g;
            int n = n0 + wn + ni * 8 + qd * 2;
            float* c4 = acc[mi][ni];
            epi(m,     n,     c4[0]);
            epi(m,     n + 1, c4[1]);
            epi(m + 8, n,     c4[2]);
            epi(m + 8, n + 1, c4[3]);
        }
}

/* ------------------------- ALiBi softmax ------------------------------ */
/* writes tf32-rounded probabilities in place */
__global__ void softmax_alibi_kernel(float* __restrict__ att) {
    __shared__ float sh[32];
    int i = blockIdx.x;
    int bh = blockIdx.y;
    int h = bh & (NH - 1);
    float slope = exp2f(-0.5f * (float)(h + 1));
    float* row = att + ((long long)bh * SEQ + i) * SEQ;
    int t = threadIdx.x;
    float v[4]; float mx = -1e30f;
    #pragma unroll
    for (int a = 0; a < 4; a++) {
        int j = t + a * 256;
        float dist = (j > i) ? (float)(j - i) : 0.f;
        v[a] = row[j] * 0.125f - slope * dist;
        mx = fmaxf(mx, v[a]);
    }
    mx = blockMax(mx, sh);
    float s = 0.f;
    #pragma unroll
    for (int a = 0; a < 4; a++) { v[a] = expf(v[a] - mx); s += v[a]; }
    s = blockSum(s, sh);
    float inv = 1.f / s;
    #pragma unroll
    for (int a = 0; a < 4; a++) row[t + a * 256] = roundtf(v[a] * inv);
}

/* ------------------- router top-2, gather lists, aux ------------------ */
__global__ void zero_aux_kernel(float* a, int* c) {
    if (threadIdx.x < 8) a[threadIdx.x] = 0.f;
    if (threadIdx.x < NE) c[threadIdx.x] = 0;
}

__global__ void topk_kernel(const float* __restrict__ gl,
                            int* __restrict__ cnt, int* __restrict__ list,
                            float* __restrict__ wl, float* __restrict__ aux) {
    int t0 = blockIdx.x * blockDim.x + threadIdx.x;
    float g[4];
    #pragma unroll
    for (int e = 0; e < 4; e++) g[e] = gl[t0 * 4 + e];
    float mx = fmaxf(fmaxf(g[0], g[1]), fmaxf(g[2], g[3]));
    float s = 0.f;
    #pragma unroll
    for (int e = 0; e < 4; e++) { g[e] = expf(g[e] - mx); s += g[e]; }
    float inv = 1.f / s;
    #pragma unroll
    for (int e = 0; e < 4; e++) g[e] *= inv;
    int i1 = 0;
    #pragma unroll
    for (int e = 1; e < 4; e++) if (g[e] > g[i1]) i1 = e;
    int i2 = (i1 == 0) ? 1 : 0;
    #pragma unroll
    for (int e = 0; e < 4; e++) if (e != i1 && g[e] > g[i2]) i2 = e;
    float sm = g[i1] + g[i2]; if (sm < 1e-9f) sm = 1e-9f;
    int s1 = atomicAdd(&cnt[i1], 1);
    list[i1 * TKN + s1] = t0; wl[i1 * TKN + s1] = g[i1] / sm;
    int s2 = atomicAdd(&cnt[i2], 1);
    list[i2 * TKN + s2] = t0; wl[i2 * TKN + s2] = g[i2] / sm;
    #pragma unroll
    for (int e = 0; e < 4; e++) {
        float v = g[e];
        #pragma unroll
        for (int o = 16; o > 0; o >>= 1) v += __shfl_xor_sync(0xffffffffu, v, o);
        if ((threadIdx.x & 31) == 0) atomicAdd(&aux[e], v);
    }
}

__global__ void aux_kernel(const float* __restrict__ sums, const int* __restrict__ cnt,
                           float* __restrict__ out, long long pos) {
    float a = 0.f;
    #pragma unroll
    for (int e = 0; e < 4; e++)
        a += (sums[e] / (float)TKN) * ((float)cnt[e] / (float)TKN);
    out[pos] = (float)NE * a;
}

/* ---------------- final: out = xs + dwconv5(Tr) + tb ------------------ */
__global__ void final_kernel(const float* __restrict__ xs, const float* __restrict__ Tr,
                             const float* __restrict__ tw, const float* __restrict__ tb,
                             float* __restrict__ out) {
    int d = blockIdx.x * 256 + threadIdx.x;
    int n = blockIdx.y, b = blockIdx.z;
    long long idx = ((long long)b * SEQ + n) * DM + d;
    float acc = tb[d];
    #pragma unroll
    for (int t = 0; t < 5; t++) {
        int src = n + t - 2;
        if (src >= 0 && src < SEQ)
            acc += Tr[((long long)b * SEQ + src) * DM + d] * tw[d * 5 + t];
    }
    out[idx] = xs[idx] + acc;
}

/* ------------------------------- host --------------------------------- */
static void launch_gemm(const float* A, const float* B, const float* bias,
                        const float* resid, const float* rowScale, int rsStride,
                        const int* rowIdx, const int* cntP,
                        float* C, int M, int N, int K,
                        long long sA, long long sB, long long sC, int batch, int flags) {
    dim3 grid((N + 127) / 128, (M + 127) / 128, batch);
    gemm_tc<<<grid, 256, GEMM_SMEM>>>(A, B, bias, resid, rowScale, rsStride,
                                      rowIdx, cntP, C, M, N, K, sA, sB, sC, flags);
}

static void round_copy(const float* src, float* dst, long long n) {
    int n4 = (int)(n / 4);
    round_copy_kernel<<<(n4 + 255) / 256, 256>>>(src, dst, n4);
}

extern "C" void kernel_launch(void* const* d_in, const int* in_sizes, int n_in,
                              void* d_out, int out_size) {
    const float* x        = (const float*)d_in[0];
    const float* qw       = (const float*)d_in[1];
    const float* qb       = (const float*)d_in[2];
    const float* kw       = (const float*)d_in[3];
    const float* kb       = (const float*)d_in[4];
    const float* vw       = (const float*)d_in[5];
    const float* vb       = (const float*)d_in[6];
    const float* ow       = (const float*)d_in[7];
    const float* ob       = (const float*)d_in[8];
    const float* n1g      = (const float*)d_in[9];
    const float* n1b      = (const float*)d_in[10];
    const float* n2g      = (const float*)d_in[11];
    const float* n2b      = (const float*)d_in[12];
    const float* alpha    = (const float*)d_in[13];
    const float* dw7      = (const float*)d_in[14];
    const float* dw25     = (const float*)d_in[15];
    const float* dw49     = (const float*)d_in[16];
    const float* router_w = (const float*)d_in[17];
    const float* ew1      = (const float*)d_in[18];
    const float* eb1      = (const float*)d_in[19];
    const float* ew2      = (const float*)d_in[20];
    const float* eb2      = (const float*)d_in[21];
    const float* tw       = (const float*)d_in[22];
    const float* tb       = (const float*)d_in[23];
    float* out = (float*)d_out;

    cudaFuncSetAttribute(gemm_tc, cudaFuncAttributeMaxDynamicSharedMemorySize, GEMM_SMEM);

    float *pTr, *pS, *pSn, *pq, *pk, *pvt, *patt, *pyt, *pxs, *pxf, *pg, *ph, *paux, *pwl;
    float *pwq, *pwk, *pwv, *pwo, *pwr, *pwe1, *pwe2;
    int *pcnt, *plist;
    cudaGetSymbolAddress((void**)&pTr,  g_Tr);
    cudaGetSymbolAddress((void**)&pS,   g_S);
    cudaGetSymbolAddress((void**)&pSn,  g_Sn);
    cudaGetSymbolAddress((void**)&pq,   g_q);
    cudaGetSymbolAddress((void**)&pk,   g_k);
    cudaGetSymbolAddress((void**)&pvt,  g_vt);
    cudaGetSymbolAddress((void**)&patt, g_att);
    cudaGetSymbolAddress((void**)&pyt,  g_yt);
    cudaGetSymbolAddress((void**)&pxs,  g_xs);
    cudaGetSymbolAddress((void**)&pxf,  g_xf);
    cudaGetSymbolAddress((void**)&pg,   g_gates);
    cudaGetSymbolAddress((void**)&ph,   g_hbuf);
    cudaGetSymbolAddress((void**)&paux, g_aux);
    cudaGetSymbolAddress((void**)&pwl,  g_wl);
    cudaGetSymbolAddress((void**)&pcnt, g_cnt);
    cudaGetSymbolAddress((void**)&plist, g_list);
    cudaGetSymbolAddress((void**)&pwq,  g_wq);
    cudaGetSymbolAddress((void**)&pwk,  g_wk);
    cudaGetSymbolAddress((void**)&pwv,  g_wv);
    cudaGetSymbolAddress((void**)&pwo,  g_wo);
    cudaGetSymbolAddress((void**)&pwr,  g_wr);
    cudaGetSymbolAddress((void**)&pwe1, g_we1);
    cudaGetSymbolAddress((void**)&pwe2, g_we2);

    /* 0. pre-round all GEMM weights to tf32 */
    round_copy(qw, pwq, (long long)DM * DM);
    round_copy(kw, pwk, (long long)DM * DM);
    round_copy(vw, pwv, (long long)DM * DM);
    round_copy(ow, pwo, (long long)DM * DM);
    round_copy(router_w, pwr, (long long)NE * DM);
    round_copy(ew1, pwe1, (long long)NE * MH * DM);
    round_copy(ew2, pwe2, (long long)NE * DM * MH);

    /* 1. decomposition: Tr, S */
    trend_kernel<<<dim3(DM / 256, SEQ, BB), 256>>>(x, dw7, dw25, dw49, alpha, pTr, pS);
    /* 2. Sn = LN(S), tf32-rounded */
    ln_kernel<<<TKN, 256>>>(pS, pSn, n1g, n1b, 1);
    /* 3. q,k -> [b,h,n,d] ; v -> [b,h,d,n] (transposed), all tf32-rounded */
    launch_gemm(pSn, pwq, qb, nullptr, nullptr, 0, nullptr, nullptr,
                pq, TKN, DM, DM, 0, 0, 0, 1, FLAG_PERM | FLAG_ROUND);
    launch_gemm(pSn, pwk, kb, nullptr, nullptr, 0, nullptr, nullptr,
                pk, TKN, DM, DM, 0, 0, 0, 1, FLAG_PERM | FLAG_ROUND);
    launch_gemm(pSn, pwv, vb, nullptr, nullptr, 0, nullptr, nullptr,
                pvt, TKN, DM, DM, 0, 0, 0, 1, FLAG_PERMT | FLAG_ROUND);
    /* 4. logits = q @ k^T (batched over 128 (b,h)) */
    launch_gemm(pq, pk, nullptr, nullptr, nullptr, 0, nullptr, nullptr, patt,
                SEQ, SEQ, HD, (long long)SEQ * HD, (long long)SEQ * HD,
                (long long)SEQ * SEQ, BB * NH, 0);
    /* 5. scale + ALiBi + softmax (in place, rounded) */
    softmax_alibi_kernel<<<dim3(SEQ, BB * NH), 256>>>(patt);
    /* 6. y = probs @ vt^T -> yt [b,n,h*d] directly (rounded) */
    launch_gemm(patt, pvt, nullptr, nullptr, nullptr, 0, nullptr, nullptr, pyt,
                SEQ, HD, SEQ, (long long)SEQ * SEQ, (long long)HD * SEQ,
                0, BB * NH, FLAG_PERMY | FLAG_ROUND);
    /* 7. O projection with residual S -> xs */
    launch_gemm(pyt, pwo, ob, pS, nullptr, 0, nullptr, nullptr,
                pxs, TKN, DM, DM, 0, 0, 0, 1, 0);
    /* 8. MoE input LN, tf32-rounded */
    ln_kernel<<<TKN, 256>>>(pxs, pxf, n2g, n2b, 1);
    /* 9. router logits, top-2 gating + gather lists + aux sums */
    launch_gemm(pxf, pwr, nullptr, nullptr, nullptr, 0, nullptr, nullptr,
                pg, TKN, NE, DM, 0, 0, 0, 1, 0);
    zero_aux_kernel<<<1, 32>>>(paux, pcnt);
    topk_kernel<<<TKN / 256, 256>>>(pg, pcnt, plist, pwl, paux);
    /* 10. experts: gather -> GEMM1(GELU, rounded) -> GEMM2 scatter+acc */
    for (int e = 0; e < NE; e++) {
        launch_gemm(pxf, pwe1 + (long long)e * MH * DM, eb1 + e * MH,
                    nullptr, nullptr, 0, plist + e * TKN, pcnt + e,
                    ph, TKN, MH, DM, 0, 0, 0, 1, FLAG_GELU | FLAG_GATHER | FLAG_ROUND);
        launch_gemm(ph, pwe2 + (long long)e * DM * MH, eb2 + e * DM,
                    nullptr, pwl + e * TKN, 1, plist + e * TKN, pcnt + e,
                    pxs, TKN, DM, MH, 0, 0, 0, 1, FLAG_ACCUM | FLAG_SCATTER);
    }
    /* 11. final: xs + trend conv, plus aux scalar */
    final_kernel<<<dim3(DM / 256, SEQ, BB), 256>>>(pxs, pTr, tw, tb, out);
    if (out_size > TKN * DM)
        aux_kernel<<<1, 1>>>(paux, pcnt, out, (long long)TKN * DM);
}